// round 3
// baseline (speedup 1.0000x reference)
#include <cuda_runtime.h>
#include <cstdint>
#include <cstddef>

#define NN   10000
#define NP   10048
#define DD   128

// ---------------- device scratch ----------------
__device__ float g_xn[(size_t)NP*DD];
__device__ float g_sim[(size_t)NP*NP];
__device__ int   g_knn[(size_t)NN*16];
__device__ float g_mult[(size_t)2048*NP];   // 4 branches *16*16 + 32*32, layout [i][j][NP]
__device__ float g_coef[(size_t)96*NP];     // [j][NP] per branch
__device__ float g_hyper[(size_t)NN*5*DD];

__device__ __forceinline__ unsigned long long kmax64(unsigned long long a, unsigned long long b){
    return a > b ? a : b;
}

// ---------------- normalize rows ----------------
__global__ __launch_bounds__(256) void k_norm(const float* __restrict__ feats){
    int w = threadIdx.x >> 5, lane = threadIdx.x & 31;
    int row = blockIdx.x*8 + w;
    if (row >= NP) return;
    if (row < NN){
        float4 v = *(const float4*)(feats + (size_t)row*DD + lane*4);
        float ss = v.x*v.x + v.y*v.y + v.z*v.z + v.w*v.w;
        #pragma unroll
        for (int o=16;o;o>>=1) ss += __shfl_xor_sync(0xffffffffu, ss, o);
        float inv = 1.0f / fmaxf(sqrtf(ss), 1e-12f);
        v.x*=inv; v.y*=inv; v.z*=inv; v.w*=inv;
        *(float4*)(g_xn + (size_t)row*DD + lane*4) = v;
    } else {
        *(float4*)(g_xn + (size_t)row*DD + lane*4) = make_float4(0.f,0.f,0.f,0.f);
    }
}

// ---------------- sim = xn @ xn^T ----------------
__global__ __launch_bounds__(256) void k_sim(){
    __shared__ float As[32][68];
    __shared__ float Bs[32][68];
    int tid = threadIdx.x;
    int tx = tid & 15, ty = tid >> 4;
    const float* Ab = g_xn + (size_t)blockIdx.y*64*DD;
    const float* Bb = g_xn + (size_t)blockIdx.x*64*DD;
    float acc[4][4];
    #pragma unroll
    for (int r=0;r<4;r++)
        #pragma unroll
        for (int c=0;c<4;c++) acc[r][c]=0.f;

    for (int k0=0;k0<DD;k0+=32){
        #pragma unroll
        for (int l=0;l<2;l++){
            int e = tid + l*256;
            int row = e >> 3, d4 = e & 7;
            float4 a = *(const float4*)(Ab + (size_t)row*DD + k0 + d4*4);
            As[d4*4+0][row]=a.x; As[d4*4+1][row]=a.y; As[d4*4+2][row]=a.z; As[d4*4+3][row]=a.w;
            float4 b = *(const float4*)(Bb + (size_t)row*DD + k0 + d4*4);
            Bs[d4*4+0][row]=b.x; Bs[d4*4+1][row]=b.y; Bs[d4*4+2][row]=b.z; Bs[d4*4+3][row]=b.w;
        }
        __syncthreads();
        #pragma unroll
        for (int dd=0; dd<32; dd++){
            float4 ra = *(const float4*)&As[dd][ty*4];
            float4 rb = *(const float4*)&Bs[dd][tx*4];
            float a_[4] = {ra.x,ra.y,ra.z,ra.w};
            float b_[4] = {rb.x,rb.y,rb.z,rb.w};
            #pragma unroll
            for (int r=0;r<4;r++)
                #pragma unroll
                for (int c=0;c<4;c++) acc[r][c] += a_[r]*b_[c];
        }
        __syncthreads();
    }
    size_t ro = (size_t)blockIdx.y*64 + ty*4;
    int    co = blockIdx.x*64 + tx*4;
    #pragma unroll
    for (int r=0;r<4;r++)
        *(float4*)(g_sim + (ro+r)*NP + co) =
            make_float4(acc[r][0], acc[r][1], acc[r][2], acc[r][3]);
}

// ---------------- per-row top-16 ----------------
__global__ __launch_bounds__(128) void k_topk(){
    __shared__ unsigned long long sk[128*16];
    __shared__ unsigned long long red[128];
    int row = blockIdx.x;
    int tid = threadIdx.x;
    const float* srow = g_sim + (size_t)row*NP;

    unsigned long long t[16];
    #pragma unroll
    for (int r=0;r<16;r++) t[r]=0ull;

    for (int j=tid; j<NN; j+=128){
        float v = srow[j];
        unsigned u = __float_as_uint(v);
        u = (u & 0x80000000u) ? ~u : (u | 0x80000000u);
        unsigned long long key = ((unsigned long long)u << 32) | (unsigned)(~(unsigned)j);
        if (key > t[15]){
            t[15] = key;
            #pragma unroll
            for (int r=15;r>0;r--){
                if (t[r] > t[r-1]){ unsigned long long tmp=t[r-1]; t[r-1]=t[r]; t[r]=tmp; }
            }
        }
    }
    #pragma unroll
    for (int r=0;r<16;r++) sk[tid*16+r] = t[r];
    __syncthreads();

    for (int sel=0; sel<16; sel++){
        unsigned long long m = sk[tid*16];
        #pragma unroll
        for (int r=1;r<16;r++) m = kmax64(m, sk[tid*16+r]);
        red[tid] = m;
        __syncthreads();
        for (int s=64;s>0;s>>=1){
            if (tid < s) red[tid] = kmax64(red[tid], red[tid+s]);
            __syncthreads();
        }
        unsigned long long best = red[0];
        if (tid == 0) g_knn[(size_t)row*16 + sel] = (int)(~(unsigned)(best & 0xffffffffull));
        #pragma unroll
        for (int r=0;r<16;r++) if (sk[tid*16+r] == best) sk[tid*16+r] = 0ull;
        __syncthreads();
    }
}

// ---------------- mult logits: mult[i][j][n] = <x[n,i], wKK[i,j]> + bKK ----
// grid (NP/64, K, K/16), block 256
template<int K>
__global__ __launch_bounds__(256) void k_mult(const float* __restrict__ feats,
                                              const int* __restrict__ idx,
                                              int stride, int off0,
                                              const float* __restrict__ wKK,
                                              const float* __restrict__ bKK,
                                              size_t moff){
    __shared__ float4 xsT[32][65];
    __shared__ float  ws[16][128];
    __shared__ float  bsh[16];
    const int tid = threadIdx.x;
    const int i = blockIdx.y;
    const int jc = blockIdx.z;
    const int n0 = blockIdx.x*64;

    for (int e=tid; e<16*32; e+=256){
        int jl = e>>5, d4 = e&31;
        float4 v = *(const float4*)(wKK + ((size_t)(i*K + jc*16 + jl))*DD + d4*4);
        *(float4*)&ws[jl][d4*4] = v;
    }
    if (tid < 16) bsh[tid] = bKK[i*K + jc*16 + tid];

    for (int e=tid; e<64*32; e+=256){
        int nn = e>>5, d4 = e&31;
        int n = n0 + nn;
        int src;
        if (idx == nullptr) src = (n < NN) ? g_knn[(size_t)n*16 + i] : 0;
        else                src = (n < NN) ? idx[(size_t)n*stride + off0 + i] : 0;
        xsT[d4][nn] = *(const float4*)(feats + (size_t)src*DD + d4*4);
    }
    __syncthreads();

    const int n  = tid & 63;
    const int jg = tid >> 6;
    float acc[4] = {0.f,0.f,0.f,0.f};
    #pragma unroll
    for (int d4=0; d4<32; d4++){
        float4 xv = xsT[d4][n];
        #pragma unroll
        for (int jj=0; jj<4; jj++){
            float4 w = *(const float4*)&ws[jg*4+jj][d4*4];
            acc[jj] += xv.x*w.x + xv.y*w.y + xv.z*w.z + xv.w*w.w;
        }
    }
    float* mout = g_mult + moff;
    #pragma unroll
    for (int jj=0; jj<4; jj++){
        int jglob = jc*16 + jg*4 + jj;
        mout[((size_t)(i*K + jglob))*NP + n0 + n] = acc[jj] + bsh[jg*4+jj];
    }
}

// ---------------- coef[j][n] = sum_i wK1[i]*softmax_j(mult[i][:,n]) ---------
template<int K>
__global__ __launch_bounds__(256) void k_coef(size_t moff, size_t coff,
                                              const float* __restrict__ wK1){
    int n = blockIdx.x*256 + threadIdx.x;
    if (n >= NN) return;
    const float* mout = g_mult + moff;
    float cacc[K];
    #pragma unroll
    for (int j=0;j<K;j++) cacc[j]=0.f;
    #pragma unroll
    for (int i=0;i<K;i++){
        float v[K];
        float m = -1e30f;
        #pragma unroll
        for (int j=0;j<K;j++){
            v[j] = mout[((size_t)(i*K + j))*NP + n];
            m = fmaxf(m, v[j]);
        }
        float s = 0.f;
        #pragma unroll
        for (int j=0;j<K;j++){ v[j] = __expf(v[j]-m); s += v[j]; }
        float w = wK1[i] / s;
        #pragma unroll
        for (int j=0;j<K;j++) cacc[j] += w * v[j];
    }
    float* cout = g_coef + coff;
    #pragma unroll
    for (int j=0;j<K;j++) cout[(size_t)j*NP + n] = cacc[j];
}

// ---------------- hyper[n][t][:] = sum_j coef[j][n]*feats[idx(n,j)] + bK1 ---
template<int K>
__global__ __launch_bounds__(256) void k_hyper(const float* __restrict__ feats,
                                               const int* __restrict__ idx,
                                               int stride, int off0,
                                               size_t coff,
                                               const float* __restrict__ bK1,
                                               int t){
    int w = threadIdx.x >> 5, lane = threadIdx.x & 31;
    int n = blockIdx.x*8 + w;
    if (n >= NN) return;
    const float* coef = g_coef + coff;
    float4 acc = make_float4(0.f,0.f,0.f,0.f);
    #pragma unroll 4
    for (int j=0;j<K;j++){
        float c = __ldg(&coef[(size_t)j*NP + n]);
        int src = (idx == nullptr) ? g_knn[(size_t)n*16 + j]
                                   : idx[(size_t)n*stride + off0 + j];
        float4 f = *(const float4*)(feats + (size_t)src*DD + lane*4);
        acc.x += c*f.x; acc.y += c*f.y; acc.z += c*f.z; acc.w += c*f.w;
    }
    float b = bK1[0];
    acc.x += b; acc.y += b; acc.z += b; acc.w += b;
    *(float4*)(g_hyper + ((size_t)n*5 + t)*DD + lane*4) = acc;
}

// ---------------- EdgeConv attention + final FC ----------------
// block 128 (4 warps, 1 n per warp), grid 2500, dynamic smem
__global__ __launch_bounds__(128) void k_final(const float* __restrict__ ec_w1,
                                               const float* __restrict__ ec_b1,
                                               const float* __restrict__ ec_w2,
                                               const float* __restrict__ ec_b2,
                                               const float* __restrict__ fc_w,
                                               const float* __restrict__ fc_b,
                                               float* __restrict__ out){
    extern __shared__ float smem[];
    float* fcw  = smem;                 // 16384 floats
    float* w1s  = smem + 16384;         // 4096 floats
    float* xs   = smem + 16384 + 4096;  // 4*640
    float* aggs = xs + 4*640;           // 4*128
    int tid = threadIdx.x;
    for (int e=tid; e<16384/4; e+=128)
        *(float4*)&fcw[e*4] = *(const float4*)&fc_w[e*4];
    for (int e=tid; e<4096/4; e+=128)
        *(float4*)&w1s[e*4] = *(const float4*)&ec_w1[e*4];
    __syncthreads();

    int w = tid >> 5, lane = tid & 31;
    int n = blockIdx.x*4 + w;

    float4 xr[5];
    #pragma unroll
    for (int t=0;t<5;t++){
        xr[t] = *(const float4*)(g_hyper + ((size_t)n*5 + t)*DD + lane*4);
        *(float4*)&xs[w*640 + t*128 + lane*4] = xr[t];
    }
    __syncwarp();

    float w2v = ec_w2[lane];
    float b1v = ec_b1[lane];
    float sc[5];
    #pragma unroll
    for (int t=0;t<5;t++){
        float h = b1v;
        #pragma unroll 4
        for (int d=0; d<DD; d++)
            h += xs[w*640 + t*128 + d] * w1s[d*32 + lane];
        h = fmaxf(h, 0.f);
        float p = h * w2v;
        #pragma unroll
        for (int o=16;o;o>>=1) p += __shfl_xor_sync(0xffffffffu, p, o);
        sc[t] = p;
    }
    float b2 = ec_b2[0];
    float m = -1e30f;
    #pragma unroll
    for (int t=0;t<5;t++){ sc[t] += b2; m = fmaxf(m, sc[t]); }
    float s = 0.f;
    #pragma unroll
    for (int t=0;t<5;t++){ sc[t] = __expf(sc[t]-m); s += sc[t]; }
    float inv = 1.f/s;
    #pragma unroll
    for (int t=0;t<5;t++) sc[t] *= inv;

    float4 a = make_float4(0.f,0.f,0.f,0.f);
    #pragma unroll
    for (int t=0;t<5;t++){
        a.x += sc[t]*xr[t].x; a.y += sc[t]*xr[t].y;
        a.z += sc[t]*xr[t].z; a.w += sc[t]*xr[t].w;
    }
    *(float4*)&aggs[w*128 + lane*4] = a;
    __syncwarp();

    float4 o = *(const float4*)&fc_b[lane*4];
    #pragma unroll 4
    for (int d=0; d<DD; d++){
        float av = aggs[w*128 + d];
        float4 fw = *(const float4*)&fcw[d*128 + lane*4];
        o.x += av*fw.x; o.y += av*fw.y; o.z += av*fw.z; o.w += av*fw.w;
    }
    o.x = fmaxf(o.x,0.f); o.y = fmaxf(o.y,0.f);
    o.z = fmaxf(o.z,0.f); o.w = fmaxf(o.w,0.f);
    *(float4*)(out + (size_t)n*DD + lane*4) = o;
}

// ---------------- launch ----------------
extern "C" void kernel_launch(void* const* d_in, const int* in_sizes, int n_in,
                              void* d_out, int out_size){
    const float* feats  = (const float*)d_in[1];
    const int*   cidx   = (const int*)d_in[2];
    const int*   sidx   = (const int*)d_in[3];
    const float* wKK_c  = (const float*)d_in[5];
    const float* bKK_c  = (const float*)d_in[6];
    const float* wK1_c  = (const float*)d_in[7];
    const float* bK1_c  = (const float*)d_in[8];
    const float* wKK_n  = (const float*)d_in[9];
    const float* bKK_n  = (const float*)d_in[10];
    const float* wK1_n  = (const float*)d_in[11];
    const float* bK1_n  = (const float*)d_in[12];
    const float* wKK_s  = (const float*)d_in[13];
    const float* bKK_s  = (const float*)d_in[14];
    const float* wK1_s  = (const float*)d_in[15];
    const float* bK1_s  = (const float*)d_in[16];
    const float* ec_w1  = (const float*)d_in[17];
    const float* ec_b1  = (const float*)d_in[18];
    const float* ec_w2  = (const float*)d_in[19];
    const float* ec_b2  = (const float*)d_in[20];
    const float* fc_w   = (const float*)d_in[21];
    const float* fc_b   = (const float*)d_in[22];
    float* out = (float*)d_out;

    cudaFuncSetAttribute(k_final, cudaFuncAttributeMaxDynamicSharedMemorySize, 94208);

    k_norm<<<NP/8, 256>>>(feats);
    k_sim<<<dim3(NP/64, NP/64), 256>>>();
    k_topk<<<NN, 128>>>();

    const size_t M16 = (size_t)256*NP;
    // cluster branches
    for (int c=0;c<3;c++)
        k_mult<16><<<dim3(NP/64,16,1),256>>>(feats, cidx, 48, c*16, wKK_c, bKK_c, (size_t)c*M16);
    // knn (idx=nullptr -> g_knn)
    k_mult<16><<<dim3(NP/64,16,1),256>>>(feats, nullptr, 16, 0, wKK_n, bKK_n, 3*M16);
    // struct
    k_mult<32><<<dim3(NP/64,32,2),256>>>(feats, sidx, 32, 0, wKK_s, bKK_s, 4*M16);

    int cb = (NN + 255)/256;
    for (int c=0;c<3;c++)
        k_coef<16><<<cb,256>>>((size_t)c*M16, (size_t)c*16*NP, wK1_c);
    k_coef<16><<<cb,256>>>(3*M16, (size_t)48*NP, wK1_n);
    k_coef<32><<<cb,256>>>(4*M16, (size_t)64*NP, wK1_s);

    for (int c=0;c<3;c++)
        k_hyper<16><<<NN/8,256>>>(feats, cidx, 48, c*16, (size_t)c*16*NP, bK1_c, c);
    k_hyper<16><<<NN/8,256>>>(feats, nullptr, 16, 0, (size_t)48*NP, bK1_n, 3);
    k_hyper<32><<<NN/8,256>>>(feats, sidx, 32, 0, (size_t)64*NP, bK1_s, 4);

    k_final<<<NN/4, 128, 94208>>>(ec_w1, ec_b1, ec_w2, ec_b2, fc_w, fc_b, out);
}